// round 5
// baseline (speedup 1.0000x reference)
#include <cuda_runtime.h>
#include <cuda_bf16.h>
#include <cstdint>

#define BB 4
#define HH 256
#define CC 80
#define TX 256
#define TY 1024
#define NEGV (-1e9f)

// Output layout (float32):
#define OFF_OEN  0
#define OFF_LOGP 1048576
#define OFF_ATTN 2097152
#define OFF_DR   3145728

// -------- device scratch --------
__device__ float g_A  [BB*CC*TX];
__device__ float g_Bc [BB*CC*TX];
__device__ float g_cst[BB*TX];
__device__ float g_lpT[BB*TY*TX];   // masked logp, transposed [b][y][x]
__device__ int   g_idx[BB*TY];      // alignment index per y (-1 = inactive)

__device__ __forceinline__ void cp_async16(void* smem_dst, const void* gmem_src) {
    unsigned sa = (unsigned)__cvta_generic_to_shared(smem_dst);
    asm volatile("cp.async.cg.shared.global [%0], [%1], 16;\n"
                 :: "r"(sa), "l"(gmem_src));
}

// =====================================================================
// K1: per-(b,x) channel precompute
// =====================================================================
__global__ void k_pre(const float* __restrict__ mu,
                      const float* __restrict__ ls) {
    int b = blockIdx.x;
    int x = threadIdx.x;
    float s3 = 0.f, sl = 0.f;
    #pragma unroll 4
    for (int c = 0; c < CC; c++) {
        int o = (b * CC + c) * TX + x;
        float l = ls[o];
        float m = mu[o];
        float w = expf(-2.0f * l);
        g_A [o] = (-0.5f / (float)CC) * w;
        g_Bc[o] = (1.0f / (float)CC) * w * m;
        s3 += w * m * m;
        sl += l;
    }
    g_cst[b * TX + x] = (-0.5f / (float)CC) * (s3 + sl);
}

// =====================================================================
// K2: logp GEMM  logp[b,x,y] = sum_c A*y^2 + B*y + cst
// =====================================================================
#define TSX 64
#define TSY 64
#define KCH 40

__global__ __launch_bounds__(256, 2)
void k_logp(const float* __restrict__ y,
            const int* __restrict__ xl,
            const int* __restrict__ yl,
            float* __restrict__ out) {
    __shared__ float sA [KCH][TSX];
    __shared__ float sB [KCH][TSX];
    __shared__ float sY [KCH][TSY];
    __shared__ float sY2[KCH][TSY];

    int b  = blockIdx.z;
    int x0 = blockIdx.y * TSX;
    int y0 = blockIdx.x * TSY;
    int tid = threadIdx.x;
    int ty = tid & 15;
    int tx = tid >> 4;
    int xr = tx * 4;
    int yc = ty * 4;

    float acc[4][4] = {};

    for (int kc = 0; kc < CC; kc += KCH) {
        __syncthreads();
        #pragma unroll
        for (int i = tid; i < KCH * TSX; i += 256) {
            int c = i >> 6, j = i & 63;
            int oa = (b * CC + (kc + c)) * TX + x0 + j;
            sA[c][j] = g_A[oa];
            sB[c][j] = g_Bc[oa];
            float yv = y[(b * CC + (kc + c)) * TY + y0 + j];
            sY [c][j] = yv;
            sY2[c][j] = yv * yv;
        }
        __syncthreads();

        #pragma unroll 8
        for (int c = 0; c < KCH; c++) {
            float4 a  = *(const float4*)&sA [c][xr];
            float4 bb = *(const float4*)&sB [c][xr];
            float4 yv = *(const float4*)&sY [c][yc];
            float4 y2 = *(const float4*)&sY2[c][yc];
            float av[4] = {a.x, a.y, a.z, a.w};
            float bv[4] = {bb.x, bb.y, bb.z, bb.w};
            float yvv[4] = {yv.x, yv.y, yv.z, yv.w};
            float y2v[4] = {y2.x, y2.y, y2.z, y2.w};
            #pragma unroll
            for (int i = 0; i < 4; i++)
                #pragma unroll
                for (int j = 0; j < 4; j++) {
                    acc[i][j] = fmaf(av[i], y2v[j], acc[i][j]);
                    acc[i][j] = fmaf(bv[i], yvv[j], acc[i][j]);
                }
        }
    }

    float cst_i[4];
    #pragma unroll
    for (int i = 0; i < 4; i++)
        cst_i[i] = g_cst[b * TX + x0 + xr + i];

    int xlen = xl[b], ylen = yl[b];

    #pragma unroll
    for (int i = 0; i < 4; i++) {
        int gx = x0 + xr + i;
        float4 r;
        r.x = acc[i][0] + cst_i[i];
        r.y = acc[i][1] + cst_i[i];
        r.z = acc[i][2] + cst_i[i];
        r.w = acc[i][3] + cst_i[i];
        *(float4*)&out[OFF_LOGP + ((size_t)(b * TX + gx)) * TY + y0 + yc] = r;
    }

    #pragma unroll
    for (int j = 0; j < 4; j++) {
        int gy = y0 + yc + j;
        bool ym = gy < ylen;
        float4 t;
        t.x = (ym && (x0 + xr + 0) < xlen) ? acc[0][j] + cst_i[0] : NEGV;
        t.y = (ym && (x0 + xr + 1) < xlen) ? acc[1][j] + cst_i[1] : NEGV;
        t.z = (ym && (x0 + xr + 2) < xlen) ? acc[2][j] + cst_i[2] : NEGV;
        t.w = (ym && (x0 + xr + 3) < xlen) ? acc[3][j] + cst_i[3] : NEGV;
        *(float4*)&g_lpT[((size_t)(b * TY + gy)) * TX + x0 + xr] = t;
    }
}

// =====================================================================
// K3: Viterbi DP — 4 specialized warps.
//   w0: recurrence only (v rows -> smem ring)
//   w1,w2: diag bits from ring (off critical path)
//   w3: cp.async producer, 3-deep chunk pipeline
// =====================================================================
#define DPC 32
// smem layout (bytes):
//   rows: float4[3][32*64]  = 98304
//   ring: float4[64][64]    = 65536  @ 98304
//   diag: unsigned[32][256] = 32768  @ 163840
//   dr:   int[256]                   @ 196608
//   cum:  int[257]                   @ 197632
#define DP_SMEM_BYTES 198660

#define BAR_ARRIVE(id) asm volatile("bar.arrive %0, 96;" :: "r"(id) : "memory")
#define BAR_SYNC(id)   asm volatile("bar.sync %0, 96;"   :: "r"(id) : "memory")

__global__ __launch_bounds__(128, 1)
void k_dp(const int* __restrict__ xl,
          const int* __restrict__ yl,
          float* __restrict__ out) {
    extern __shared__ char smem[];
    float4*   rows  = (float4*)smem;                      // [3][2048]
    float4*   ring  = (float4*)(smem + 98304);            // [64][64]
    unsigned* diag  = (unsigned*)(smem + 163840);         // [32][256]
    int*      s_dr  = (int*)(smem + 196608);
    int*      s_cum = (int*)(smem + 197632);

    int b    = blockIdx.x;
    int tid  = threadIdx.x;
    int wid  = tid >> 5;
    int lane = tid & 31;

    int xlen = xl[b], ylen = yl[b];
    int nck  = (ylen + DPC - 1) / DPC;     // 16..32 chunks of 32 steps

    const float4* lp4 = (const float4*)(g_lpT + (size_t)b * TY * TX);

    s_dr[tid] = 0; s_dr[tid + 128] = 0;

    if (wid == 0) {
        // seed ring slot 63 with v_init (read by diag warps for y=0)
        float4 z0 = make_float4(NEGV, NEGV, NEGV, NEGV);
        float4 z1 = z0;
        if (lane == 0) z0.x = 0.0f;
        ring[63 * 64 + lane * 2]     = z0;
        ring[63 * 64 + lane * 2 + 1] = z1;
    } else if (wid == 3) {
        // prologue: chunks 0 and 1
        for (int i = lane; i < 2048; i += 32) cp_async16(rows + i, lp4 + i);
        asm volatile("cp.async.commit_group;\n");
        for (int i = lane; i < 2048; i += 32) cp_async16(rows + 2048 + i, lp4 + 2048 + i);
        asm volatile("cp.async.commit_group;\n");
        asm volatile("cp.async.wait_group 1;\n" ::: "memory");
    }
    __syncthreads();

    if (wid == 0) {
        // ---------------- consumer: pure recurrence ----------------
        float v[8];
        #pragma unroll
        for (int i = 0; i < 8; i++) v[i] = NEGV;
        if (lane == 0) v[0] = 0.0f;

        float4 c0 = rows[lane * 2], c1 = rows[lane * 2 + 1];
        int y = 0;

        for (int ck = 0; ck < nck; ck++) {
            const float4* rb  = rows + (ck % 3) * 2048;
            const float4* rbn = rows + ((ck + 1) % 3) * 2048;

            #pragma unroll
            for (int half = 0; half < 2; half++) {
                #pragma unroll
                for (int r16 = 0; r16 < 16; r16++) {
                    const int r = half * 16 + r16;
                    const float4* pf = (r < 31) ? rb + (r + 1) * 64 : rbn;
                    float4 n0 = pf[lane * 2];
                    float4 n1 = pf[lane * 2 + 1];

                    float top = __shfl_up_sync(0xffffffffu, v[7], 1);
                    if (lane == 0) top = NEGV;

                    float cc[8] = {c0.x, c0.y, c0.z, c0.w,
                                   c1.x, c1.y, c1.z, c1.w};
                    #pragma unroll
                    for (int i = 7; i >= 1; i--)
                        v[i] = cc[i] + fmaxf(v[i], v[i - 1]);
                    v[0] = cc[0] + fmaxf(v[0], top);

                    float4* rrp = ring + (y & 63) * 64;
                    rrp[lane * 2]     = make_float4(v[0], v[1], v[2], v[3]);
                    rrp[lane * 2 + 1] = make_float4(v[4], v[5], v[6], v[7]);

                    c0 = n0; c1 = n1; y++;
                }
                __threadfence_block();
                BAR_ARRIVE(3 + half);
            }
            __syncthreads();
        }
    } else if (wid < 3) {
        // ---------------- diag warps: bits from ring ----------------
        int xq = (wid - 1) * 32 + lane;        // float4 index within a row
        for (int ck = 0; ck < nck; ck++) {
            unsigned db0 = 0, db1 = 0, db2 = 0, db3 = 0;
            #pragma unroll
            for (int half = 0; half < 2; half++) {
                BAR_SYNC(3 + half);
                #pragma unroll
                for (int r16 = 0; r16 < 16; r16++) {
                    int yy = ck * 32 + half * 16 + r16;
                    const float4* pr = ring + ((yy - 1) & 63) * 64;
                    float4 V = pr[xq];
                    float pm1 = __shfl_up_sync(0xffffffffu, V.w, 1);
                    if (lane == 0)
                        pm1 = (wid == 1) ? NEGV : ((const float*)pr)[127];
                    unsigned bit = 1u << (half * 16 + r16);
                    if (pm1 > V.x) db0 |= bit;
                    if (V.x > V.y) db1 |= bit;
                    if (V.y > V.z) db2 |= bit;
                    if (V.z > V.w) db3 |= bit;
                }
            }
            *(uint4*)&diag[ck * 256 + xq * 4] = make_uint4(db0, db1, db2, db3);
            __syncthreads();
        }
    } else {
        // ---------------- producer: chunk ck+2 each iteration ----------------
        for (int ck = 0; ck < nck; ck++) {
            if (ck + 2 < nck) {
                const float4* src = lp4 + (ck + 2) * 2048;
                float4* dst = rows + ((ck + 2) % 3) * 2048;
                for (int i = lane; i < 2048; i += 32)
                    cp_async16(dst + i, src + i);
                asm volatile("cp.async.commit_group;\n");
                asm volatile("cp.async.wait_group 1;\n" ::: "memory");
            } else {
                asm volatile("cp.async.wait_group 0;\n" ::: "memory");
            }
            __syncthreads();
        }
    }
    __syncthreads();

    // ---- backtrack: run-length over diag words (lane 0) ----
    if (tid == 0) {
        int idx = xlen - 1;
        int yy  = ylen - 1;
        while (yy >= 0) {
            if (idx == 0) { s_dr[0] += yy + 1; break; }
            int yw = yy >> 5;
            unsigned mask = ((yy & 31) == 31) ? 0xffffffffu
                                              : ((2u << (yy & 31)) - 1u);
            unsigned m = diag[yw * 256 + idx] & mask;
            if (m) {
                int ystar = (yw << 5) + (31 - __clz(m));
                s_dr[idx] += yy - ystar + 1;
                idx--;
                yy = ystar - 1;
            } else {
                s_dr[idx] += yy - (yw << 5) + 1;
                yy = (yw << 5) - 1;
            }
        }
    }
    __syncthreads();

    // ---- exclusive cumsum of durations (warp 0) ----
    if (wid == 0) {
        int t[8], run[8];
        int tot = 0;
        #pragma unroll
        for (int i = 0; i < 8; i++) {
            t[i] = s_dr[lane * 8 + i];
            tot += t[i];
            run[i] = tot;
        }
        int sc = tot;
        #pragma unroll
        for (int d = 1; d < 32; d <<= 1) {
            int n = __shfl_up_sync(0xffffffffu, sc, d);
            if (lane >= d) sc += n;
        }
        int excl = sc - tot;
        if (lane == 0) s_cum[0] = 0;
        #pragma unroll
        for (int i = 0; i < 8; i++)
            s_cum[lane * 8 + i + 1] = excl + run[i];

        #pragma unroll
        for (int i = 0; i < 8; i++)
            out[OFF_DR + b * TX + lane * 8 + i] = (float)t[i];
    }
    __syncthreads();

    // ---- g_idx via binary search (8 y per thread) ----
    #pragma unroll
    for (int k = 0; k < TY / 128; k++) {
        int yy = k * 128 + tid;
        int r = -1;
        if (yy < ylen) {
            int lo = 0, hi = TX - 1;
            #pragma unroll
            for (int s = 0; s < 8; s++) {
                int mid = (lo + hi) >> 1;
                if (yy >= s_cum[mid + 1]) lo = mid + 1; else hi = mid;
            }
            r = lo;
        }
        g_idx[b * TY + yy] = r;
    }
}

// =====================================================================
// K4: fused epilogue — 4 rows per block
// =====================================================================
__global__ __launch_bounds__(256)
void k_epi(const float* __restrict__ en, float* __restrict__ out) {
    __shared__ float se[4][TX];
    int bid = blockIdx.x;
    int tid = threadIdx.x;
    int row0 = bid * 4;

    if (row0 < BB * TX) {
        // attn rows row0..row0+3, same batch b
        int b = row0 >> 8;
        int4 id = *(const int4*)&g_idx[b * TY + tid * 4];
        #pragma unroll
        for (int rr = 0; rr < 4; rr++) {
            int x = (row0 + rr) & 255;
            float4 r;
            r.x = (id.x == x) ? 1.0f : 0.0f;
            r.y = (id.y == x) ? 1.0f : 0.0f;
            r.z = (id.z == x) ? 1.0f : 0.0f;
            r.w = (id.w == x) ? 1.0f : 0.0f;
            *(float4*)&out[OFF_ATTN + (size_t)(row0 + rr) * TY + tid * 4] = r;
        }
    } else {
        int r0 = row0 - BB * TX;          // oen row group
        int b  = r0 >> 8;
        {   // stage 4 en rows: thread tid -> row rr=tid/64, float4 (tid&63)
            int rr = tid >> 6;
            int h  = (r0 + rr) & 255;
            *(float4*)&se[rr][(tid & 63) * 4] =
                *(const float4*)&en[(b * HH + h) * TX + (tid & 63) * 4];
        }
        __syncthreads();
        int4 id = *(const int4*)&g_idx[b * TY + tid * 4];
        #pragma unroll
        for (int rr = 0; rr < 4; rr++) {
            float4 r;
            r.x = (id.x >= 0) ? se[rr][id.x] : 0.0f;
            r.y = (id.y >= 0) ? se[rr][id.y] : 0.0f;
            r.z = (id.z >= 0) ? se[rr][id.z] : 0.0f;
            r.w = (id.w >= 0) ? se[rr][id.w] : 0.0f;
            *(float4*)&out[OFF_OEN + (size_t)(r0 + rr) * TY + tid * 4] = r;
        }
    }
}

// =====================================================================
extern "C" void kernel_launch(void* const* d_in, const int* in_sizes, int n_in,
                              void* d_out, int out_size) {
    const float* en = (const float*)d_in[0];
    const float* mu = (const float*)d_in[1];
    const float* ls = (const float*)d_in[2];
    const float* y  = (const float*)d_in[3];
    const int*   xl = (const int*)d_in[4];
    const int*   yl = (const int*)d_in[5];
    float* out = (float*)d_out;

    cudaFuncSetAttribute(k_dp, cudaFuncAttributeMaxDynamicSharedMemorySize,
                         DP_SMEM_BYTES);

    k_pre<<<BB, TX>>>(mu, ls);

    dim3 g2(TY / TSY, TX / TSX, BB);   // (16, 4, 4)
    k_logp<<<g2, 256>>>(y, xl, yl, out);

    k_dp<<<BB, 128, DP_SMEM_BYTES>>>(xl, yl, out);

    k_epi<<<2 * BB * TX / 4, 256>>>(en, out);
}

// round 6
// speedup vs baseline: 1.0933x; 1.0933x over previous
#include <cuda_runtime.h>
#include <cuda_bf16.h>
#include <cstdint>

#define BB 4
#define HH 256
#define CC 80
#define TX 256
#define TY 1024
#define NEGV (-1e9f)

// Output layout (float32):
#define OFF_OEN  0
#define OFF_LOGP 1048576
#define OFF_ATTN 2097152
#define OFF_DR   3145728

// -------- device scratch --------
__device__ float g_A  [BB*CC*TX];
__device__ float g_Bc [BB*CC*TX];
__device__ float g_cst[BB*TX];
__device__ float g_lpT[BB*TY*TX];   // masked logp, transposed [b][y][x]
__device__ int   g_idx[BB*TY];      // alignment index per y (-1 = inactive)

__device__ __forceinline__ void cp_async16(void* smem_dst, const void* gmem_src) {
    unsigned sa = (unsigned)__cvta_generic_to_shared(smem_dst);
    asm volatile("cp.async.cg.shared.global [%0], [%1], 16;\n"
                 :: "r"(sa), "l"(gmem_src));
}

// =====================================================================
// K1: per-(b,x) channel precompute
// =====================================================================
__global__ void k_pre(const float* __restrict__ mu,
                      const float* __restrict__ ls) {
    int b = blockIdx.x;
    int x = threadIdx.x;
    float s3 = 0.f, sl = 0.f;
    #pragma unroll 4
    for (int c = 0; c < CC; c++) {
        int o = (b * CC + c) * TX + x;
        float l = ls[o];
        float m = mu[o];
        float w = expf(-2.0f * l);
        g_A [o] = (-0.5f / (float)CC) * w;
        g_Bc[o] = (1.0f / (float)CC) * w * m;
        s3 += w * m * m;
        sl += l;
    }
    g_cst[b * TX + x] = (-0.5f / (float)CC) * (s3 + sl);
}

// =====================================================================
// K2: logp GEMM  logp[b,x,y] = sum_c A*y^2 + B*y + cst
// =====================================================================
#define TSX 64
#define TSY 64
#define KCH 40

__global__ __launch_bounds__(256, 2)
void k_logp(const float* __restrict__ y,
            const int* __restrict__ xl,
            const int* __restrict__ yl,
            float* __restrict__ out) {
    __shared__ float sA [KCH][TSX];
    __shared__ float sB [KCH][TSX];
    __shared__ float sY [KCH][TSY];
    __shared__ float sY2[KCH][TSY];

    int b  = blockIdx.z;
    int x0 = blockIdx.y * TSX;
    int y0 = blockIdx.x * TSY;
    int tid = threadIdx.x;
    int ty = tid & 15;
    int tx = tid >> 4;
    int xr = tx * 4;
    int yc = ty * 4;

    float acc[4][4] = {};

    for (int kc = 0; kc < CC; kc += KCH) {
        __syncthreads();
        #pragma unroll
        for (int i = tid; i < KCH * TSX; i += 256) {
            int c = i >> 6, j = i & 63;
            int oa = (b * CC + (kc + c)) * TX + x0 + j;
            sA[c][j] = g_A[oa];
            sB[c][j] = g_Bc[oa];
            float yv = y[(b * CC + (kc + c)) * TY + y0 + j];
            sY [c][j] = yv;
            sY2[c][j] = yv * yv;
        }
        __syncthreads();

        #pragma unroll 8
        for (int c = 0; c < KCH; c++) {
            float4 a  = *(const float4*)&sA [c][xr];
            float4 bb = *(const float4*)&sB [c][xr];
            float4 yv = *(const float4*)&sY [c][yc];
            float4 y2 = *(const float4*)&sY2[c][yc];
            float av[4] = {a.x, a.y, a.z, a.w};
            float bv[4] = {bb.x, bb.y, bb.z, bb.w};
            float yvv[4] = {yv.x, yv.y, yv.z, yv.w};
            float y2v[4] = {y2.x, y2.y, y2.z, y2.w};
            #pragma unroll
            for (int i = 0; i < 4; i++)
                #pragma unroll
                for (int j = 0; j < 4; j++) {
                    acc[i][j] = fmaf(av[i], y2v[j], acc[i][j]);
                    acc[i][j] = fmaf(bv[i], yvv[j], acc[i][j]);
                }
        }
    }

    float cst_i[4];
    #pragma unroll
    for (int i = 0; i < 4; i++)
        cst_i[i] = g_cst[b * TX + x0 + xr + i];

    int xlen = xl[b], ylen = yl[b];

    #pragma unroll
    for (int i = 0; i < 4; i++) {
        int gx = x0 + xr + i;
        float4 r;
        r.x = acc[i][0] + cst_i[i];
        r.y = acc[i][1] + cst_i[i];
        r.z = acc[i][2] + cst_i[i];
        r.w = acc[i][3] + cst_i[i];
        *(float4*)&out[OFF_LOGP + ((size_t)(b * TX + gx)) * TY + y0 + yc] = r;
    }

    #pragma unroll
    for (int j = 0; j < 4; j++) {
        int gy = y0 + yc + j;
        bool ym = gy < ylen;
        float4 t;
        t.x = (ym && (x0 + xr + 0) < xlen) ? acc[0][j] + cst_i[0] : NEGV;
        t.y = (ym && (x0 + xr + 1) < xlen) ? acc[1][j] + cst_i[1] : NEGV;
        t.z = (ym && (x0 + xr + 2) < xlen) ? acc[2][j] + cst_i[2] : NEGV;
        t.w = (ym && (x0 + xr + 3) < xlen) ? acc[3][j] + cst_i[3] : NEGV;
        *(float4*)&g_lpT[((size_t)(b * TY + gy)) * TX + x0 + xr] = t;
    }
}

// =====================================================================
// K3: Viterbi DP — 4 specialized warps, 1 __syncthreads per 32-step chunk.
//   w0: recurrence only, v rows -> triple-buffered vring (2 STS.128/step)
//   w1,w2: diag bits from vring, one chunk behind consumer
//   w3: cp.async producer, triple-buffered rows, depth-2 pipeline
// =====================================================================
#define DPC 32
// smem layout (bytes):
//   rows:  float4[3][32*64]  = 98304   @ 0
//   vring: float4[3][32*64]  = 98304   @ 98304
//   diag:  unsigned[32][256] = 32768   @ 196608
//   dr:    int[256]          = 1024    @ 229376
//   cum:   int[257]          = 1028    @ 230400
#define DP_SMEM_BYTES 231456

__global__ __launch_bounds__(128, 1)
void k_dp(const int* __restrict__ xl,
          const int* __restrict__ yl,
          float* __restrict__ out) {
    extern __shared__ char smem[];
    float4*   rows  = (float4*)smem;                      // [3][2048]
    float4*   vring = (float4*)(smem + 98304);            // [3][2048]
    unsigned* diag  = (unsigned*)(smem + 196608);         // [32][256]
    int*      s_dr  = (int*)(smem + 229376);
    int*      s_cum = (int*)(smem + 230400);

    int b    = blockIdx.x;
    int tid  = threadIdx.x;
    int wid  = tid >> 5;
    int lane = tid & 31;

    int xlen = xl[b], ylen = yl[b];
    int nck  = (ylen + DPC - 1) / DPC;     // 16..32 chunks of 32 steps

    const float4* lp4 = (const float4*)(g_lpT + (size_t)b * TY * TX);

    s_dr[tid] = 0; s_dr[tid + 128] = 0;

    if (wid == 0) {
        // seed "row -1" = v_init into vring buffer 2, row 31
        float4 z0 = make_float4(NEGV, NEGV, NEGV, NEGV);
        float4 z1 = z0;
        if (lane == 0) z0.x = 0.0f;
        vring[2 * 2048 + 31 * 64 + lane * 2]     = z0;
        vring[2 * 2048 + 31 * 64 + lane * 2 + 1] = z1;
    } else if (wid == 3) {
        // prologue: chunks 0 and 1 into rows[0], rows[1]
        for (int i = lane; i < 2048; i += 32) cp_async16(rows + i, lp4 + i);
        asm volatile("cp.async.commit_group;\n");
        for (int i = lane; i < 2048; i += 32)
            cp_async16(rows + 2048 + i, lp4 + 2048 + i);
        asm volatile("cp.async.commit_group;\n");
        asm volatile("cp.async.wait_group 1;\n" ::: "memory");  // chunk 0 done
    }
    __syncthreads();                                   // barrier #0

    if (wid == 0) {
        // ---------------- consumer: pure recurrence ----------------
        float v[8];
        #pragma unroll
        for (int i = 0; i < 8; i++) v[i] = NEGV;
        if (lane == 0) v[0] = 0.0f;

        float4 c0 = rows[lane * 2], c1 = rows[lane * 2 + 1];

        #pragma unroll 1
        for (int ck = 0; ck < nck; ck++) {
            const float4* rb = rows  + (ck % 3) * 2048;
            float4*       vr = vring + (ck % 3) * 2048;

            #pragma unroll
            for (int r = 0; r < 32; r++) {
                float4 n0, n1;
                if (r < 31) {
                    n0 = rb[(r + 1) * 64 + lane * 2];
                    n1 = rb[(r + 1) * 64 + lane * 2 + 1];
                }
                float top = __shfl_up_sync(0xffffffffu, v[7], 1);
                if (lane == 0) top = NEGV;

                float cc[8] = {c0.x, c0.y, c0.z, c0.w,
                               c1.x, c1.y, c1.z, c1.w};
                #pragma unroll
                for (int i = 7; i >= 1; i--)
                    v[i] = cc[i] + fmaxf(v[i], v[i - 1]);
                v[0] = cc[0] + fmaxf(v[0], top);

                vr[r * 64 + lane * 2]     = make_float4(v[0], v[1], v[2], v[3]);
                vr[r * 64 + lane * 2 + 1] = make_float4(v[4], v[5], v[6], v[7]);

                if (r < 31) { c0 = n0; c1 = n1; }
            }
            __syncthreads();                           // barrier #ck+1
            if (ck + 1 < nck) {
                c0 = rows[((ck + 1) % 3) * 2048 + lane * 2];
                c1 = rows[((ck + 1) % 3) * 2048 + lane * 2 + 1];
            }
        }
    } else if (wid < 3) {
        // ---------------- diag warps: bits from vring, 1 chunk behind ----
        int xq = (wid - 1) * 32 + lane;        // float4 index within a row
        bool l0 = (lane == 0);
        #pragma unroll 1
        for (int ck = 0; ck < nck; ck++) {
            __syncthreads();                           // barrier #ck+1
            const float4* vr    = vring + (ck % 3) * 2048;
            const float4* vprev = vring + ((ck + 2) % 3) * 2048;
            unsigned db0 = 0, db1 = 0, db2 = 0, db3 = 0;
            #pragma unroll
            for (int r = 0; r < 32; r++) {
                const float4* pr = (r == 0) ? (vprev + 31 * 64)
                                            : (vr + (r - 1) * 64);
                float4 V = pr[xq];
                float pm1 = __shfl_up_sync(0xffffffffu, V.w, 1);
                if (l0) pm1 = (wid == 1) ? NEGV : ((const float*)pr)[127];
                unsigned bit = 1u << r;
                if (pm1 > V.x) db0 |= bit;
                if (V.x > V.y) db1 |= bit;
                if (V.y > V.z) db2 |= bit;
                if (V.z > V.w) db3 |= bit;
            }
            *(uint4*)&diag[ck * 256 + xq * 4] = make_uint4(db0, db1, db2, db3);
        }
    } else {
        // ---------------- producer: chunk ck+2 each window ----------------
        #pragma unroll 1
        for (int ck = 0; ck < nck; ck++) {
            if (ck + 2 < nck) {
                const float4* src = lp4 + (ck + 2) * 2048;
                float4* dst = rows + ((ck + 2) % 3) * 2048;
                for (int i = lane; i < 2048; i += 32)
                    cp_async16(dst + i, src + i);
                asm volatile("cp.async.commit_group;\n");
                asm volatile("cp.async.wait_group 1;\n" ::: "memory");
            } else {
                asm volatile("cp.async.wait_group 0;\n" ::: "memory");
            }
            __syncthreads();                           // barrier #ck+1
        }
    }
    __syncthreads();   // final: diag warps finished last chunk

    // ---- backtrack: run-length over diag words (lane 0) ----
    if (tid == 0) {
        int idx = xlen - 1;
        int yy  = ylen - 1;
        while (yy >= 0) {
            if (idx == 0) { s_dr[0] += yy + 1; break; }
            int yw = yy >> 5;
            unsigned mask = ((yy & 31) == 31) ? 0xffffffffu
                                              : ((2u << (yy & 31)) - 1u);
            unsigned m = diag[yw * 256 + idx] & mask;
            if (m) {
                int ystar = (yw << 5) + (31 - __clz(m));
                s_dr[idx] += yy - ystar + 1;
                idx--;
                yy = ystar - 1;
            } else {
                s_dr[idx] += yy - (yw << 5) + 1;
                yy = (yw << 5) - 1;
            }
        }
    }
    __syncthreads();

    // ---- exclusive cumsum of durations (warp 0) ----
    if (wid == 0) {
        int t[8], run[8];
        int tot = 0;
        #pragma unroll
        for (int i = 0; i < 8; i++) {
            t[i] = s_dr[lane * 8 + i];
            tot += t[i];
            run[i] = tot;
        }
        int sc = tot;
        #pragma unroll
        for (int d = 1; d < 32; d <<= 1) {
            int n = __shfl_up_sync(0xffffffffu, sc, d);
            if (lane >= d) sc += n;
        }
        int excl = sc - tot;
        if (lane == 0) s_cum[0] = 0;
        #pragma unroll
        for (int i = 0; i < 8; i++)
            s_cum[lane * 8 + i + 1] = excl + run[i];

        #pragma unroll
        for (int i = 0; i < 8; i++)
            out[OFF_DR + b * TX + lane * 8 + i] = (float)t[i];
    }
    __syncthreads();

    // ---- g_idx via binary search (8 y per thread) ----
    #pragma unroll
    for (int k = 0; k < TY / 128; k++) {
        int yy = k * 128 + tid;
        int r = -1;
        if (yy < ylen) {
            int lo = 0, hi = TX - 1;
            #pragma unroll
            for (int s = 0; s < 8; s++) {
                int mid = (lo + hi) >> 1;
                if (yy >= s_cum[mid + 1]) lo = mid + 1; else hi = mid;
            }
            r = lo;
        }
        g_idx[b * TY + yy] = r;
    }
}

// =====================================================================
// K4: fused epilogue — 4 rows per block
// =====================================================================
__global__ __launch_bounds__(256)
void k_epi(const float* __restrict__ en, float* __restrict__ out) {
    __shared__ float se[4][TX];
    int bid = blockIdx.x;
    int tid = threadIdx.x;
    int row0 = bid * 4;

    if (row0 < BB * TX) {
        int b = row0 >> 8;
        int4 id = *(const int4*)&g_idx[b * TY + tid * 4];
        #pragma unroll
        for (int rr = 0; rr < 4; rr++) {
            int x = (row0 + rr) & 255;
            float4 r;
            r.x = (id.x == x) ? 1.0f : 0.0f;
            r.y = (id.y == x) ? 1.0f : 0.0f;
            r.z = (id.z == x) ? 1.0f : 0.0f;
            r.w = (id.w == x) ? 1.0f : 0.0f;
            *(float4*)&out[OFF_ATTN + (size_t)(row0 + rr) * TY + tid * 4] = r;
        }
    } else {
        int r0 = row0 - BB * TX;
        int b  = r0 >> 8;
        {
            int rr = tid >> 6;
            int h  = (r0 + rr) & 255;
            *(float4*)&se[rr][(tid & 63) * 4] =
                *(const float4*)&en[(b * HH + h) * TX + (tid & 63) * 4];
        }
        __syncthreads();
        int4 id = *(const int4*)&g_idx[b * TY + tid * 4];
        #pragma unroll
        for (int rr = 0; rr < 4; rr++) {
            float4 r;
            r.x = (id.x >= 0) ? se[rr][id.x] : 0.0f;
            r.y = (id.y >= 0) ? se[rr][id.y] : 0.0f;
            r.z = (id.z >= 0) ? se[rr][id.z] : 0.0f;
            r.w = (id.w >= 0) ? se[rr][id.w] : 0.0f;
            *(float4*)&out[OFF_OEN + (size_t)(r0 + rr) * TY + tid * 4] = r;
        }
    }
}

// =====================================================================
extern "C" void kernel_launch(void* const* d_in, const int* in_sizes, int n_in,
                              void* d_out, int out_size) {
    const float* en = (const float*)d_in[0];
    const float* mu = (const float*)d_in[1];
    const float* ls = (const float*)d_in[2];
    const float* y  = (const float*)d_in[3];
    const int*   xl = (const int*)d_in[4];
    const int*   yl = (const int*)d_in[5];
    float* out = (float*)d_out;

    cudaFuncSetAttribute(k_dp, cudaFuncAttributeMaxDynamicSharedMemorySize,
                         DP_SMEM_BYTES);

    k_pre<<<BB, TX>>>(mu, ls);

    dim3 g2(TY / TSY, TX / TSX, BB);   // (16, 4, 4)
    k_logp<<<g2, 256>>>(y, xl, yl, out);

    k_dp<<<BB, 128, DP_SMEM_BYTES>>>(xl, yl, out);

    k_epi<<<2 * BB * TX / 4, 256>>>(en, out);
}